// round 13
// baseline (speedup 1.0000x reference)
#include <cuda_runtime.h>
#include <cuda_bf16.h>
#include <math.h>
#include <stdint.h>

// PCL loss, single kernel:
//   valid = target != -1
//   p     = (target==0) ? input[i*21] : pc_input[cluster[i]]
//   loss  = sum(valid * (-w * log(max(p,1e-12)))) / max(sum(valid),1)
//
// R13 = R11 (smem pc table, branchless broadcast bg gather, L2-atomic tail)
// with the 16KB table fetched by ONE cp.async.bulk (TMA path):
//  * zero register cost, zero L1tex occupancy -> overlaps with the stream
//    loads without the R12 register blowup (48 regs / 53% occ regression)
//  * streams use __ldcs (evict-first) so 24MB of single-use data stays out
//    of L2, which also serves 1024 x 16KB table fills

#define C_CLASSES 21
#define EPS 1e-12f
#define NUM_CLUSTERS 4096
#define TABLE_BYTES (NUM_CLUSTERS * 4)
#define THREADS 256
#define EPT 8
#define LN2F 0.6931471805599453f

__device__ float        g_sum = 0.0f;
__device__ unsigned int g_cnt = 0u;
__device__ unsigned int g_done = 0u;   // wraps to 0 via atom.inc bound

__device__ __forceinline__ uint32_t smem_u32(const void* p) {
    uint32_t a;
    asm("{ .reg .u64 t; cvta.to.shared.u64 t, %1; cvt.u32.u64 %0, t; }"
        : "=r"(a) : "l"(p));
    return a;
}

__global__ void __launch_bounds__(THREADS)
pcl_fused(const float* __restrict__ input,
          const float* __restrict__ weight,
          const float* __restrict__ pc,
          const int* __restrict__ target,
          const int* __restrict__ cluster,
          int n, float* __restrict__ out) {
    __shared__ __align__(16) float pc_s[NUM_CLUSTERS];
    __shared__ __align__(8)  unsigned long long mbar;

    // one-shot bulk copy of the table (TMA path: no registers, no L1tex)
    if (threadIdx.x == 0) {
        uint32_t mb = smem_u32(&mbar);
        asm volatile("mbarrier.init.shared.b64 [%0], 1;" :: "r"(mb) : "memory");
        asm volatile("fence.proxy.async.shared::cta;" ::: "memory");
        asm volatile("mbarrier.arrive.expect_tx.shared.b64 _, [%0], %1;"
                     :: "r"(mb), "r"((uint32_t)TABLE_BYTES) : "memory");
        asm volatile("cp.async.bulk.shared::cta.global.mbarrier::complete_tx::bytes "
                     "[%0], [%1], %2, [%3];"
                     :: "r"(smem_u32(pc_s)), "l"(pc),
                        "r"((uint32_t)TABLE_BYTES), "r"(mb) : "memory");
    }
    __syncthreads();   // no thread may wait on the mbarrier before init

    float lsum = 0.0f;                 // accumulates w * log2(p)
    unsigned int lcnt = 0u;

    const int i = (blockIdx.x * THREADS + threadIdx.x) * EPT;

    if (i + EPT <= n) {
        // Phase A: 6 independent coalesced 128-bit stream loads (evict-first)
        int4   t4a = __ldcs(reinterpret_cast<const int4*>(target + i));
        int4   t4b = __ldcs(reinterpret_cast<const int4*>(target + i + 4));
        int4   c4a = __ldcs(reinterpret_cast<const int4*>(cluster + i));
        int4   c4b = __ldcs(reinterpret_cast<const int4*>(cluster + i + 4));
        float4 w4a = __ldcs(reinterpret_cast<const float4*>(weight + i));
        float4 w4b = __ldcs(reinterpret_cast<const float4*>(weight + i + 4));

        int   t[EPT] = {t4a.x, t4a.y, t4a.z, t4a.w, t4b.x, t4b.y, t4b.z, t4b.w};
        int   c[EPT] = {c4a.x, c4a.y, c4a.z, c4a.w, c4b.x, c4b.y, c4b.z, c4b.w};
        float w[EPT] = {w4a.x, w4a.y, w4a.z, w4a.w, w4b.x, w4b.y, w4b.z, w4b.w};

        // Phase B1: background LDG, branchless; inactive lanes -> input[0]
        // (single broadcast sector per warp-instr), 8 loads in flight
        float pbg[EPT];
        #pragma unroll
        for (int k = 0; k < EPT; k++) {
            const float* a = (t[k] == 0)
                           ? input + (long long)(i + k) * C_CLASSES
                           : input;
            pbg[k] = __ldg(a);
        }

        // table is ready by now (16KB L2 fill << stream DRAM latency)
        {
            uint32_t mb = smem_u32(&mbar);
            asm volatile(
                "{\n\t.reg .pred P;\n"
                "W_%=:\n\t"
                "mbarrier.try_wait.parity.acquire.cta.shared::cta.b64 P, [%0], 0, 0x989680;\n\t"
                "@P bra.uni D_%=;\n\t"
                "bra.uni W_%=;\n"
                "D_%=:\n\t}" :: "r"(mb) : "memory");
        }

        // Phase B2: foreground gather from smem (bank-conflict cost only)
        float pfg[EPT];
        #pragma unroll
        for (int k = 0; k < EPT; k++) {
            pfg[k] = pc_s[c[k] & (NUM_CLUSTERS - 1)];
        }

        // Phase C: select + log2 + masked accumulate
        #pragma unroll
        for (int k = 0; k < EPT; k++) {
            float p = (t[k] == 0) ? pbg[k] : pfg[k];
            bool valid = (t[k] != -1);
            float l = __log2f(fmaxf(p, EPS));
            lsum += valid ? w[k] * l : 0.0f;
            lcnt += valid ? 1u : 0u;
        }
    } else {
        // ragged tail: wait for table, then scalar path
        uint32_t mb = smem_u32(&mbar);
        asm volatile(
            "{\n\t.reg .pred P;\n"
            "W_%=:\n\t"
            "mbarrier.try_wait.parity.acquire.cta.shared::cta.b64 P, [%0], 0, 0x989680;\n\t"
            "@P bra.uni D_%=;\n\t"
            "bra.uni W_%=;\n"
            "D_%=:\n\t}" :: "r"(mb) : "memory");
        for (int k = i; k < n; k++) {
            int tk = target[k];
            if (tk != -1) {
                float pk = (tk == 0) ? __ldg(input + (long long)k * C_CLASSES)
                                     : pc_s[cluster[k] & (NUM_CLUSTERS - 1)];
                lsum += weight[k] * __log2f(fmaxf(pk, EPS));
                lcnt++;
            }
        }
    }

    // warp reduction
    #pragma unroll
    for (int off = 16; off > 0; off >>= 1) {
        lsum += __shfl_xor_sync(0xFFFFFFFFu, lsum, off);
        lcnt += __shfl_xor_sync(0xFFFFFFFFu, lcnt, off);
    }

    // block reduction (8 warps)
    __shared__ float        s_sum[8];
    __shared__ unsigned int s_cnt[8];
    __shared__ int          s_is_last;
    int wid = threadIdx.x >> 5;
    int lid = threadIdx.x & 31;
    if (lid == 0) { s_sum[wid] = lsum; s_cnt[wid] = lcnt; }
    __syncthreads();
    if (threadIdx.x == 0) {
        float        bs = 0.0f;
        unsigned int bc = 0u;
        #pragma unroll
        for (int w8 = 0; w8 < 8; w8++) { bs += s_sum[w8]; bc += s_cnt[w8]; }
        // merge partials at the L2 coherence point (atomics bypass L1)
        atomicAdd(&g_sum, bs);
        atomicAdd(&g_cnt, bc);
        // release-only inc publishes the adds; wraps to 0 at gridDim.x-1
        // (self-reset, graph-replay deterministic); no acquire => no L1 flush
        unsigned int prev;
        asm volatile("atom.release.gpu.global.inc.u32 %0, [%1], %2;"
                     : "=r"(prev)
                     : "l"(&g_done), "r"(gridDim.x - 1)
                     : "memory");
        s_is_last = (prev == gridDim.x - 1) ? 1 : 0;
    }
    __syncthreads();

    if (s_is_last && threadIdx.x == 0) {
        // coherent reads at L2 — no acquire/L1-invalidate needed
        float        ts = atomicAdd(&g_sum, 0.0f);
        unsigned int tc = atomicAdd(&g_cnt, 0u);
        float nv = fmaxf((float)tc, 1.0f);
        *out = -(ts * LN2F) / nv;      // log2 -> ln conversion, once
        g_sum = 0.0f;                  // reset for next replay (kernel
        g_cnt = 0u;                    //  boundary orders visibility)
    }
}

extern "C" void kernel_launch(void* const* d_in, const int* in_sizes, int n_in,
                              void* d_out, int out_size) {
    const float* input   = (const float*)d_in[0];   // [N, 21]
    const float* weight  = (const float*)d_in[1];   // [N]
    const float* pc      = (const float*)d_in[2];   // [4096]
    const int*   target  = (const int*)d_in[3];     // [N] int32
    const int*   cluster = (const int*)d_in[4];     // [N] int32
    float* out = (float*)d_out;

    int n = in_sizes[1];   // weight element count == N

    int per_block = THREADS * EPT;                 // 2048
    int blocks = (n + per_block - 1) / per_block;  // 1024 for N=2M
    if (blocks < 1) blocks = 1;
    pcl_fused<<<blocks, THREADS>>>(input, weight, pc, target, cluster, n, out);
}

// round 14
// speedup vs baseline: 1.0329x; 1.0329x over previous
#include <cuda_runtime.h>
#include <cuda_bf16.h>
#include <math.h>

// PCL loss, single kernel:
//   valid = target != -1
//   p     = (target==0) ? input[i*21] : pc_input[cluster[i]]
//   loss  = sum(valid * (-w * log(max(p,1e-12)))) / max(sum(valid),1)
//
// R14 = R11 (the proven local optimum: smem pc table staged BEFORE stream
// loads, plain LDG streams, branchless broadcast bg gather, L2-atomic tail)
// with one change: 512 threads/CTA instead of 256.
//  -> 512 CTAs x 16 warps: ~3.5 CTAs/SM, up to 64 resident warps (occ ~90%)
//  -> table-staging L2 traffic halved (512 x 16KB = 8MB vs 16MB)
//  -> same 32-reg footprint per thread (no __ldcs, no hoisting: both
//     regressed in R12/R13 via register pressure)

#define C_CLASSES 21
#define EPS 1e-12f
#define NUM_CLUSTERS 4096
#define THREADS 512
#define NWARPS (THREADS / 32)
#define EPT 8
#define LN2F 0.6931471805599453f

__device__ float        g_sum = 0.0f;
__device__ unsigned int g_cnt = 0u;
__device__ unsigned int g_done = 0u;   // wraps to 0 via atom.inc bound

__global__ void __launch_bounds__(THREADS)
pcl_fused(const float* __restrict__ input,
          const float* __restrict__ weight,
          const float* __restrict__ pc,
          const int* __restrict__ target,
          const int* __restrict__ cluster,
          int n, float* __restrict__ out) {
    __shared__ float pc_s[NUM_CLUSTERS];

    // stage the 16KB pc table (L2-resident after first wave): 2 float4/thread
    {
        const float4* src = reinterpret_cast<const float4*>(pc);
        #pragma unroll
        for (int k = 0; k < NUM_CLUSTERS / 4 / THREADS; k++) {
            int idx = k * THREADS + threadIdx.x;
            float4 v = __ldg(src + idx);
            *reinterpret_cast<float4*>(pc_s + idx * 4) = v;
        }
    }
    __syncthreads();

    float lsum = 0.0f;                 // accumulates w * log2(p)
    unsigned int lcnt = 0u;

    const int i = (blockIdx.x * THREADS + threadIdx.x) * EPT;

    if (i + EPT <= n) {
        // Phase A: 6 independent coalesced 128-bit loads
        int4   t4a = *reinterpret_cast<const int4*>(target + i);
        int4   t4b = *reinterpret_cast<const int4*>(target + i + 4);
        int4   c4a = *reinterpret_cast<const int4*>(cluster + i);
        int4   c4b = *reinterpret_cast<const int4*>(cluster + i + 4);
        float4 w4a = *reinterpret_cast<const float4*>(weight + i);
        float4 w4b = *reinterpret_cast<const float4*>(weight + i + 4);

        int   t[EPT] = {t4a.x, t4a.y, t4a.z, t4a.w, t4b.x, t4b.y, t4b.z, t4b.w};
        int   c[EPT] = {c4a.x, c4a.y, c4a.z, c4a.w, c4b.x, c4b.y, c4b.z, c4b.w};
        float w[EPT] = {w4a.x, w4a.y, w4a.z, w4a.w, w4b.x, w4b.y, w4b.z, w4b.w};

        // Phase B1: background LDG, branchless; inactive lanes -> input[0]
        // (single broadcast sector per warp-instr), 8 loads in flight
        float pbg[EPT];
        #pragma unroll
        for (int k = 0; k < EPT; k++) {
            const float* a = (t[k] == 0)
                           ? input + (long long)(i + k) * C_CLASSES
                           : input;
            pbg[k] = __ldg(a);
        }
        // Phase B2: foreground gather from smem (bank-conflict cost only)
        float pfg[EPT];
        #pragma unroll
        for (int k = 0; k < EPT; k++) {
            pfg[k] = pc_s[c[k] & (NUM_CLUSTERS - 1)];
        }

        // Phase C: select + log2 + masked accumulate
        #pragma unroll
        for (int k = 0; k < EPT; k++) {
            float p = (t[k] == 0) ? pbg[k] : pfg[k];
            bool valid = (t[k] != -1);
            float l = __log2f(fmaxf(p, EPS));
            lsum += valid ? w[k] * l : 0.0f;
            lcnt += valid ? 1u : 0u;
        }
    } else {
        for (int k = i; k < n; k++) {
            int tk = target[k];
            if (tk != -1) {
                float pk = (tk == 0) ? __ldg(input + (long long)k * C_CLASSES)
                                     : pc_s[cluster[k] & (NUM_CLUSTERS - 1)];
                lsum += weight[k] * __log2f(fmaxf(pk, EPS));
                lcnt++;
            }
        }
    }

    // warp reduction
    #pragma unroll
    for (int off = 16; off > 0; off >>= 1) {
        lsum += __shfl_xor_sync(0xFFFFFFFFu, lsum, off);
        lcnt += __shfl_xor_sync(0xFFFFFFFFu, lcnt, off);
    }

    // block reduction (16 warps)
    __shared__ float        s_sum[NWARPS];
    __shared__ unsigned int s_cnt[NWARPS];
    __shared__ int          s_is_last;
    int wid = threadIdx.x >> 5;
    int lid = threadIdx.x & 31;
    if (lid == 0) { s_sum[wid] = lsum; s_cnt[wid] = lcnt; }
    __syncthreads();
    if (threadIdx.x == 0) {
        float        bs = 0.0f;
        unsigned int bc = 0u;
        #pragma unroll
        for (int w8 = 0; w8 < NWARPS; w8++) { bs += s_sum[w8]; bc += s_cnt[w8]; }
        // merge partials at the L2 coherence point (atomics bypass L1)
        atomicAdd(&g_sum, bs);
        atomicAdd(&g_cnt, bc);
        // release-only inc publishes the adds; wraps to 0 at gridDim.x-1
        // (self-reset, graph-replay deterministic); no acquire => no L1 flush
        unsigned int prev;
        asm volatile("atom.release.gpu.global.inc.u32 %0, [%1], %2;"
                     : "=r"(prev)
                     : "l"(&g_done), "r"(gridDim.x - 1)
                     : "memory");
        s_is_last = (prev == gridDim.x - 1) ? 1 : 0;
    }
    __syncthreads();

    if (s_is_last && threadIdx.x == 0) {
        // coherent reads at L2 — no acquire/L1-invalidate needed
        float        ts = atomicAdd(&g_sum, 0.0f);
        unsigned int tc = atomicAdd(&g_cnt, 0u);
        float nv = fmaxf((float)tc, 1.0f);
        *out = -(ts * LN2F) / nv;      // log2 -> ln conversion, once
        g_sum = 0.0f;                  // reset for next replay (kernel
        g_cnt = 0u;                    //  boundary orders visibility)
    }
}

extern "C" void kernel_launch(void* const* d_in, const int* in_sizes, int n_in,
                              void* d_out, int out_size) {
    const float* input   = (const float*)d_in[0];   // [N, 21]
    const float* weight  = (const float*)d_in[1];   // [N]
    const float* pc      = (const float*)d_in[2];   // [4096]
    const int*   target  = (const int*)d_in[3];     // [N] int32
    const int*   cluster = (const int*)d_in[4];     // [N] int32
    float* out = (float*)d_out;

    int n = in_sizes[1];   // weight element count == N

    int per_block = THREADS * EPT;                 // 4096
    int blocks = (n + per_block - 1) / per_block;  // 512 for N=2M
    if (blocks < 1) blocks = 1;
    pcl_fused<<<blocks, THREADS>>>(input, weight, pc, target, cluster, n, out);
}